// round 2
// baseline (speedup 1.0000x reference)
#include <cuda_runtime.h>

#define BATCH 128
#define DIMZ  128
#define NELEM 3072
#define MPAD  4096
#define NCH   24
#define CW    128   // chunk width: NCH*CW == NELEM

// ---------------- scratch (static device globals; no allocation) -----------
__device__ float g_xs[BATCH * NELEM];        // sorted rows of x
__device__ float g_inv[BATCH];               // 1/max(||z_i||, eps)
__device__ float g_zcos[BATCH * BATCH];      // cosine similarity matrix
__device__ int   g_maxbits;                  // float-as-int max of g_zcos (max > 0)
__device__ float g_part[NCH * BATCH * BATCH];// split-K EMD partial sums
__device__ float g_loss;                     // accumulated squared error

// ---------------- kernels --------------------------------------------------
__global__ void k_init() {
    g_loss = 0.f;
    g_maxbits = 0;  // true max >= 1.0 > 0, so 0-bits init is safe for int-bit max
}

__global__ void k_norm(const float* __restrict__ z) {
    int r = threadIdx.x;
    const float* zr = z + r * DIMZ;
    float s = 0.f;
    #pragma unroll 8
    for (int k = 0; k < DIMZ; k++) { float v = zr[k]; s += v * v; }
    g_inv[r] = 1.f / fmaxf(sqrtf(s), 1e-12f);
}

// Bitonic sort of one row (3072 real + 1024 +inf pad) per block, 1024 threads.
__global__ void k_sort(const float* __restrict__ x) {
    __shared__ float s[MPAD];
    int t = threadIdx.x;
    int row = blockIdx.x;
    const float* xr = x + row * NELEM;
    s[t]        = xr[t];
    s[t + 1024] = xr[t + 1024];
    s[t + 2048] = xr[t + 2048];
    s[t + 3072] = __int_as_float(0x7f800000);  // +inf pad
    __syncthreads();

    for (int k = 2; k <= MPAD; k <<= 1) {
        for (int j = k >> 1; j > 0; j >>= 1) {
            #pragma unroll
            for (int mm = 0; mm < 2; mm++) {
                int m = t + mm * 1024;                       // comparator id 0..2047
                int i = ((m & ~(j - 1)) << 1) | (m & (j - 1)); // insert 0-bit at j
                int l = i | j;
                bool asc = ((i & k) == 0);
                float a = s[i], b = s[l];
                float lo = fminf(a, b), hi = fmaxf(a, b);
                s[i] = asc ? lo : hi;
                s[l] = asc ? hi : lo;
            }
            __syncthreads();
        }
    }

    float* out = g_xs + row * NELEM;
    out[t]        = s[t];
    out[t + 1024] = s[t + 1024];
    out[t + 2048] = s[t + 2048];
}

// One block per row i; thread j computes cos(i,j). Also block-max -> global max.
__global__ void k_zcos(const float* __restrict__ z) {
    __shared__ float zi[DIMZ];
    __shared__ float red[4];
    int i = blockIdx.x, j = threadIdx.x;
    zi[j] = z[i * DIMZ + j] * g_inv[i];
    __syncthreads();
    const float* zj = z + j * DIMZ;
    float dot = 0.f;
    #pragma unroll 8
    for (int k = 0; k < DIMZ; k++) dot += zi[k] * zj[k];
    float c = dot * g_inv[j];
    g_zcos[i * BATCH + j] = c;

    float m = c;
    #pragma unroll
    for (int o = 16; o; o >>= 1) m = fmaxf(m, __shfl_xor_sync(0xffffffffu, m, o));
    if ((j & 31) == 0) red[j >> 5] = m;
    __syncthreads();
    if (j == 0) {
        float mx = fmaxf(fmaxf(red[0], red[1]), fmaxf(red[2], red[3]));
        atomicMax(&g_maxbits, __float_as_int(mx));  // mx > 0 -> int-order monotonic
    }
}

// Split-K EMD partials. grid (4,4,NCH), 256 threads; each thread a 2x2 pair tile.
__global__ void k_emd() {
    __shared__ float sa[32 * 129];
    __shared__ float sb[32 * 129];
    int tid = threadIdx.x;
    int i0 = blockIdx.y * 32, j0 = blockIdx.x * 32, c0 = blockIdx.z * CW;

    for (int idx = tid; idx < 32 * CW; idx += 256) {
        int r = idx >> 7, c = idx & (CW - 1);
        sa[r * 129 + c] = g_xs[(i0 + r) * NELEM + c0 + c];
        sb[r * 129 + c] = g_xs[(j0 + r) * NELEM + c0 + c];
    }
    __syncthreads();

    int ty = tid >> 4, tx = tid & 15;
    const float* pa0 = sa + (2 * ty) * 129;
    const float* pa1 = pa0 + 129;
    const float* pb0 = sb + (2 * tx) * 129;
    const float* pb1 = pb0 + 129;

    float s00 = 0.f, s01 = 0.f, s10 = 0.f, s11 = 0.f;
    #pragma unroll 8
    for (int c = 0; c < CW; c++) {
        float a0 = pa0[c], a1 = pa1[c];
        float b0 = pb0[c], b1 = pb1[c];
        s00 += fabsf(a0 - b0);
        s01 += fabsf(a0 - b1);
        s10 += fabsf(a1 - b0);
        s11 += fabsf(a1 - b1);
    }

    float* out = g_part + blockIdx.z * (BATCH * BATCH);
    int ri = i0 + 2 * ty, rj = j0 + 2 * tx;
    out[ri * BATCH + rj]           = s00;
    out[ri * BATCH + rj + 1]       = s01;
    out[(ri + 1) * BATCH + rj]     = s10;
    out[(ri + 1) * BATCH + rj + 1] = s11;
}

// Combine partials, compute squared errors, reduce into g_loss. 16 x 1024.
__global__ void k_mse() {
    __shared__ float red[32];
    int idx = blockIdx.x * 1024 + threadIdx.x;
    float s = 0.f;
    #pragma unroll
    for (int ch = 0; ch < NCH; ch++) s += g_part[ch * (BATCH * BATCH) + idx];
    float emd  = s * (1.f / (float)NELEM);
    float gmax = __int_as_float(g_maxbits);
    float d = emd - (gmax - g_zcos[idx]);
    float v = d * d;
    #pragma unroll
    for (int o = 16; o; o >>= 1) v += __shfl_xor_sync(0xffffffffu, v, o);
    if ((threadIdx.x & 31) == 0) red[threadIdx.x >> 5] = v;
    __syncthreads();
    if (threadIdx.x < 32) {
        float w = red[threadIdx.x];
        #pragma unroll
        for (int o = 16; o; o >>= 1) w += __shfl_xor_sync(0xffffffffu, w, o);
        if (threadIdx.x == 0) atomicAdd(&g_loss, w);
    }
}

__global__ void k_final(float* __restrict__ out) {
    out[0] = g_loss * (1.f / (float)(BATCH * BATCH));
}

// ---------------- launch ----------------------------------------------------
extern "C" void kernel_launch(void* const* d_in, const int* in_sizes, int n_in,
                              void* d_out, int out_size) {
    const float* z = (const float*)d_in[0];
    const float* x = (const float*)d_in[1];
    // defensive: identify by element count (z = 16384, x = 393216)
    if (n_in >= 2 && in_sizes[0] == BATCH * NELEM) {
        const float* tmp = z; z = x; x = tmp;
    }

    k_init<<<1, 1>>>();
    k_norm<<<1, BATCH>>>(z);
    k_sort<<<BATCH, 1024>>>(x);
    k_zcos<<<BATCH, DIMZ>>>(z);
    dim3 ge(4, 4, NCH);
    k_emd<<<ge, 256>>>();
    k_mse<<<16, 1024>>>();
    k_final<<<1, 1>>>((float*)d_out);
}

// round 3
// speedup vs baseline: 1.8107x; 1.8107x over previous
#include <cuda_runtime.h>

#define BATCH 128
#define DIMZ  128
#define NELEM 3072
#define MPAD  4096
#define NCH   32
#define CW    96    // NCH*CW == NELEM
#define TS    97    // smem row stride for emd (odd -> conflict-free banks)

// ---------------- scratch (static device globals; no allocation) -----------
__device__ float g_xs[BATCH * NELEM];         // sorted rows of x
__device__ float g_zn[BATCH * DIMZ];          // normalized z
__device__ float g_znT[DIMZ * BATCH];         // normalized z, transposed
__device__ float g_zcos[BATCH * BATCH];       // cosine similarity matrix
__device__ int   g_maxbits;                   // float-as-int max of g_zcos (max > 0)
__device__ float g_part[NCH * BATCH * BATCH]; // split-K EMD partials
__device__ float g_loss;                      // accumulated squared error

// ---------------- kernels --------------------------------------------------
__global__ void k_init() {
    g_loss = 0.f;
    g_maxbits = 0;  // true max >= 1.0 > 0, so 0-bits init is safe for int-bit max
}

// grid 128 x 128: block r normalizes row r, writes g_zn and g_znT.
__global__ void k_norm(const float* __restrict__ z) {
    __shared__ float red[4];
    __shared__ float sinv;
    int r = blockIdx.x, t = threadIdx.x;
    float v = z[r * DIMZ + t];
    float sq = v * v;
    #pragma unroll
    for (int o = 16; o; o >>= 1) sq += __shfl_xor_sync(0xffffffffu, sq, o);
    if ((t & 31) == 0) red[t >> 5] = sq;
    __syncthreads();
    if (t == 0) {
        float s = red[0] + red[1] + red[2] + red[3];
        sinv = 1.f / fmaxf(sqrtf(s), 1e-12f);
    }
    __syncthreads();
    float zn = v * sinv;
    g_zn[r * DIMZ + t] = zn;
    g_znT[t * BATCH + r] = zn;
}

// ---------------- hybrid bitonic sort --------------------------------------
__device__ __forceinline__ void cswap(float& a, float& b, bool asc) {
    float lo = fminf(a, b), hi = fmaxf(a, b);
    a = asc ? lo : hi;
    b = asc ? hi : lo;
}

// In-register bitonic stages j = jstart .. 1 for outer stage k.
// Thread holds elements e0..e0+3; j>=4 partners via shfl within the warp.
__device__ __forceinline__ void reg_sweep(float v[4], int e0, int k, int jstart) {
    bool asc = ((e0 & k) == 0);
    for (int j = jstart; j >= 4; j >>= 1) {
        bool low = ((e0 & j) == 0);
        bool km = (low == asc);
        #pragma unroll
        for (int r = 0; r < 4; r++) {
            float o = __shfl_xor_sync(0xffffffffu, v[r], j >> 2);
            v[r] = km ? fminf(v[r], o) : fmaxf(v[r], o);
        }
    }
    if (jstart >= 2) {            // j = 2 (direction uniform in-thread, k >= 4 here)
        cswap(v[0], v[2], asc);
        cswap(v[1], v[3], asc);
    }
    {                             // j = 1 (per-pair direction; differs only at k == 2)
        bool a0 = ((e0 & k) == 0);
        bool a1 = (((e0 + 2) & k) == 0);
        cswap(v[0], v[1], a0);
        cswap(v[2], v[3], a1);
    }
}

// Sort one row (3072 real + 1024 +inf) per block, 1024 threads.
__global__ __launch_bounds__(1024, 1) void k_sort(const float* __restrict__ x) {
    __shared__ __align__(16) float s[MPAD];
    int t = threadIdx.x;
    int row = blockIdx.x;
    int e0 = t * 4;

    float v[4];
    if (e0 < NELEM) {
        float4 f = *reinterpret_cast<const float4*>(x + row * NELEM + e0);
        v[0] = f.x; v[1] = f.y; v[2] = f.z; v[3] = f.w;
    } else {
        v[0] = v[1] = v[2] = v[3] = __int_as_float(0x7f800000);
    }

    // Phase A: k = 2..128 entirely in registers (warp-local 128-elt segments).
    for (int k = 2; k <= 128; k <<= 1)
        reg_sweep(v, e0, k, k >> 1);

    *reinterpret_cast<float4*>(&s[e0]) = make_float4(v[0], v[1], v[2], v[3]);
    __syncthreads();

    // Phase B: k = 256..4096; only j >= 128 goes through shared memory.
    for (int k = 256; k <= MPAD; k <<= 1) {
        for (int j = k >> 1; j >= 128; j >>= 1) {
            #pragma unroll
            for (int mm = 0; mm < 2; mm++) {
                int m = t + (mm << 10);
                int i = ((m & ~(j - 1)) << 1) | (m & (j - 1));
                int l = i | j;
                bool asc = ((i & k) == 0);
                float a = s[i], b = s[l];
                float lo = fminf(a, b), hi = fmaxf(a, b);
                s[i] = asc ? lo : hi;
                s[l] = asc ? hi : lo;
            }
            __syncthreads();
        }
        float4 f = *reinterpret_cast<const float4*>(&s[e0]);
        v[0] = f.x; v[1] = f.y; v[2] = f.z; v[3] = f.w;
        reg_sweep(v, e0, k, 64);
        if (k < MPAD) {
            *reinterpret_cast<float4*>(&s[e0]) = make_float4(v[0], v[1], v[2], v[3]);
            __syncthreads();
        }
    }

    if (e0 < NELEM)
        *reinterpret_cast<float4*>(g_xs + row * NELEM + e0) =
            make_float4(v[0], v[1], v[2], v[3]);
}

// grid 128 x 128: block i, thread j -> cos(i,j); coalesced via g_znT.
__global__ void k_zcos() {
    __shared__ float zi[DIMZ];
    __shared__ float red[4];
    int i = blockIdx.x, j = threadIdx.x;
    zi[j] = g_zn[i * DIMZ + j];
    __syncthreads();
    float dot = 0.f;
    #pragma unroll 16
    for (int kk = 0; kk < DIMZ; kk++) dot += zi[kk] * g_znT[kk * BATCH + j];
    g_zcos[i * BATCH + j] = dot;

    float m = dot;
    #pragma unroll
    for (int o = 16; o; o >>= 1) m = fmaxf(m, __shfl_xor_sync(0xffffffffu, m, o));
    if ((j & 31) == 0) red[j >> 5] = m;
    __syncthreads();
    if (j == 0) {
        float mx = fmaxf(fmaxf(red[0], red[1]), fmaxf(red[2], red[3]));
        atomicMax(&g_maxbits, __float_as_int(mx));  // mx > 0 -> int-order monotonic
    }
}

// Split-K EMD. grid (2,2,NCH) = 128 blocks, 256 threads, 4x4 outputs/thread.
// Warp shaped 8(tx) x 4(ty): b-row LDS banks (4*tx*TS mod 32) all distinct,
// a-rows broadcast -> conflict-free.
extern __shared__ float sm_emd[];
__global__ __launch_bounds__(256, 1) void k_emd() {
    float* sa = sm_emd;
    float* sb = sm_emd + 64 * TS;
    int tid = threadIdx.x;
    int w = tid >> 5, l = tid & 31;
    int tx = (l & 7) | ((w & 1) << 3);   // 0..15
    int ty = (l >> 3) | ((w >> 1) << 2); // 0..15
    int i0 = blockIdx.y * 64, j0 = blockIdx.x * 64, c0 = blockIdx.z * CW;

    for (int idx = tid; idx < 64 * CW; idx += 256) {
        int r = idx / CW, c = idx - r * CW;
        sa[r * TS + c] = g_xs[(i0 + r) * NELEM + c0 + c];
        sb[r * TS + c] = g_xs[(j0 + r) * NELEM + c0 + c];
    }
    __syncthreads();

    float acc[16];
    #pragma unroll
    for (int q = 0; q < 16; q++) acc[q] = 0.f;

    const float* pa = sa + (ty * 4) * TS;
    const float* pb = sb + (tx * 4) * TS;
    #pragma unroll 4
    for (int c = 0; c < CW; c++) {
        float a[4], b[4];
        #pragma unroll
        for (int r = 0; r < 4; r++) a[r] = pa[r * TS + c];
        #pragma unroll
        for (int r = 0; r < 4; r++) b[r] = pb[r * TS + c];
        #pragma unroll
        for (int r = 0; r < 4; r++)
            #pragma unroll
            for (int q = 0; q < 4; q++) {
                float d = __fmaf_rn(b[q], -1.f, a[r]);        // FFMA-imm
                acc[r * 4 + q] = __fmaf_rn(fabsf(d), 1.f, acc[r * 4 + q]); // FFMA-imm, |.|
            }
    }

    float* out = g_part + blockIdx.z * (BATCH * BATCH);
    int ri = i0 + ty * 4, rj = j0 + tx * 4;
    #pragma unroll
    for (int r = 0; r < 4; r++)
        #pragma unroll
        for (int q = 0; q < 4; q++)
            out[(ri + r) * BATCH + rj + q] = acc[r * 4 + q];
}

// Combine partials, squared error, reduce into g_loss. 16 x 1024.
__global__ void k_mse() {
    __shared__ float red[32];
    int idx = blockIdx.x * 1024 + threadIdx.x;
    float s = 0.f;
    #pragma unroll
    for (int ch = 0; ch < NCH; ch++) s += g_part[ch * (BATCH * BATCH) + idx];
    float emd = s * (1.f / (float)NELEM);
    float gmax = __int_as_float(g_maxbits);
    float d = emd - (gmax - g_zcos[idx]);
    float v = d * d;
    #pragma unroll
    for (int o = 16; o; o >>= 1) v += __shfl_xor_sync(0xffffffffu, v, o);
    if ((threadIdx.x & 31) == 0) red[threadIdx.x >> 5] = v;
    __syncthreads();
    if (threadIdx.x < 32) {
        float wv = red[threadIdx.x];
        #pragma unroll
        for (int o = 16; o; o >>= 1) wv += __shfl_xor_sync(0xffffffffu, wv, o);
        if (threadIdx.x == 0) atomicAdd(&g_loss, wv);
    }
}

__global__ void k_final(float* __restrict__ out) {
    out[0] = g_loss * (1.f / (float)(BATCH * BATCH));
}

// ---------------- launch ----------------------------------------------------
extern "C" void kernel_launch(void* const* d_in, const int* in_sizes, int n_in,
                              void* d_out, int out_size) {
    const float* z = (const float*)d_in[0];
    const float* x = (const float*)d_in[1];
    if (n_in >= 2 && in_sizes[0] == BATCH * NELEM) {  // defensive swap
        const float* tmp = z; z = x; x = tmp;
    }

    static int smem_set = 0;
    int smem_emd = 2 * 64 * TS * (int)sizeof(float);  // 49664 B
    if (!smem_set) {
        cudaFuncSetAttribute(k_emd, cudaFuncAttributeMaxDynamicSharedMemorySize, smem_emd);
        smem_set = 1;
    }

    k_init<<<1, 1>>>();
    k_norm<<<BATCH, DIMZ>>>(z);
    k_sort<<<BATCH, 1024>>>(x);
    k_zcos<<<BATCH, DIMZ>>>();
    dim3 ge(2, 2, NCH);
    k_emd<<<ge, 256, smem_emd>>>();
    k_mse<<<16, 1024>>>();
    k_final<<<1, 1>>>((float*)d_out);
}